// round 7
// baseline (speedup 1.0000x reference)
#include <cuda_runtime.h>
#include <cuda_bf16.h>

#define B_  4
#define T_  2048
#define D_  512
#define H_  8
#define HD_ 64
#define BH_ (B_*H_)   // 32

// Scratch (allocation-free rule: __device__ globals)
__device__ __align__(16) float g_Qf[BH_*T_*HD_];   // [b,h,t,hd] tf32, pre-scaled 0.125
__device__ __align__(16) float g_Kt[BH_*HD_*T_];   // [b,h,hd,t] tf32 (transposed)
__device__ __align__(16) float g_Vt[BH_*HD_*T_];   // [b,h,dv,t] tf32 (transposed)
__device__ __align__(16) float g_A [B_*T_*D_];     // attention out [b,t,D], tf32-rounded

__device__ __forceinline__ float to_tf32(float x) {
    float r;
    asm("cvt.rna.tf32.f32 %0, %1;" : "=f"(r) : "f"(x));
    return r;
}

__device__ __forceinline__ void mma_tf32(float* c, const float* a, float b0, float b1) {
    asm volatile(
        "mma.sync.aligned.m16n8k8.row.col.f32.tf32.tf32.f32 "
        "{%0,%1,%2,%3},{%4,%5,%6,%7},{%8,%9},{%0,%1,%2,%3};"
        : "+f"(c[0]), "+f"(c[1]), "+f"(c[2]), "+f"(c[3])
        : "r"(__float_as_uint(a[0])), "r"(__float_as_uint(a[1])),
          "r"(__float_as_uint(a[2])), "r"(__float_as_uint(a[3])),
          "r"(__float_as_uint(b0)), "r"(__float_as_uint(b1)));
}

__device__ __forceinline__ void cp16(unsigned dst, const void* src) {
    asm volatile("cp.async.cg.shared.global [%0], [%1], 16;" :: "r"(dst), "l"(src));
}

// ===========================================================================
// tf32 mma GEMM: C[128x128] = A[128x512] * B[512x128] (+bias).
// 128 threads = 4 warps (2m x 2n), warp tile 64x64, k-tile 16,
// cp.async double-buffered, tf32 cvt at fragment read.
// EPI: 0 = plain store + bias ; 1 = qkv scatter epilogue.
// A_GA: read A from device-global g_A inside device code (a __device__
//       symbol passed as a host-side kernel arg resolves to the host shadow).
// ===========================================================================
template<int N_GL, int EPI, bool A_GA>
__global__ __launch_bounds__(128, 2) void gemm_tf32(
    const float* __restrict__ A_in,
    const float* __restrict__ B_gl,
    const float* __restrict__ bias,
    float* __restrict__ out)
{
    const int K = 512;
    const float* A_gl = A_GA ? (const float*)g_A : A_in;

    __shared__ float As[2][128][20];   // [m][k] stride 20 (== 4 mod 32), row 80B (16B-aligned)
    __shared__ float Bs[2][16][136];   // [k][n] stride 136 (== 8 mod 32), row 544B

    int bm = blockIdx.y * 128, bn = blockIdx.x * 128;
    int tid = threadIdx.x;
    int w = tid >> 5, lane = tid & 31, g = lane >> 2, t4 = lane & 3;
    int wm = (w >> 1) * 64, wn = (w & 1) * 64;

    unsigned sA = (unsigned)__cvta_generic_to_shared(&As[0][0][0]);
    unsigned sB = (unsigned)__cvta_generic_to_shared(&Bs[0][0][0]);

    int brow = tid >> 3;               // 0..15
    int bcol = (tid & 7) * 16;         // 0,16,...,112

    auto issue_tile = [&](int kt) {
        int buf = kt & 1;
        int k0 = kt * 16;
        const float* a = A_gl + (size_t)(bm + tid) * K + k0;
        unsigned da = sA + (unsigned)(buf * 128 * 20 + tid * 20) * 4;
        #pragma unroll
        for (int c = 0; c < 4; c++) cp16(da + c * 16, a + c * 4);
        const float* bsrc = B_gl + (size_t)(k0 + brow) * N_GL + bn + bcol;
        unsigned db = sB + (unsigned)(buf * 16 * 136 + brow * 136 + bcol) * 4;
        #pragma unroll
        for (int c = 0; c < 4; c++) cp16(db + c * 16, bsrc + c * 4);
        asm volatile("cp.async.commit_group;");
    };

    float acc[4][8][4];
    #pragma unroll
    for (int mt = 0; mt < 4; mt++)
        #pragma unroll
        for (int nt = 0; nt < 8; nt++)
            #pragma unroll
            for (int c = 0; c < 4; c++) acc[mt][nt][c] = 0.0f;

    issue_tile(0);

    #pragma unroll 1
    for (int kt = 0; kt < 32; kt++) {
        int cur = kt & 1;
        if (kt + 1 < 32) {
            issue_tile(kt + 1);
            asm volatile("cp.async.wait_group 1;");
        } else {
            asm volatile("cp.async.wait_group 0;");
        }
        __syncthreads();

        #pragma unroll
        for (int ks = 0; ks < 2; ks++) {
            int k0 = ks * 8;
            float af[4][4];
            #pragma unroll
            for (int mt = 0; mt < 4; mt++) {
                af[mt][0] = to_tf32(As[cur][wm + mt * 16 + g][k0 + t4]);
                af[mt][1] = to_tf32(As[cur][wm + mt * 16 + g + 8][k0 + t4]);
                af[mt][2] = to_tf32(As[cur][wm + mt * 16 + g][k0 + t4 + 4]);
                af[mt][3] = to_tf32(As[cur][wm + mt * 16 + g + 8][k0 + t4 + 4]);
            }
            #pragma unroll
            for (int nt = 0; nt < 8; nt++) {
                float b0 = to_tf32(Bs[cur][k0 + t4][wn + nt * 8 + g]);
                float b1 = to_tf32(Bs[cur][k0 + t4 + 4][wn + nt * 8 + g]);
                #pragma unroll
                for (int mt = 0; mt < 4; mt++)
                    mma_tf32(acc[mt][nt], af[mt], b0, b1);
            }
        }
        __syncthreads();   // fence reads before next issue overwrites buf^1
    }

    // Epilogue
    #pragma unroll
    for (int mt = 0; mt < 4; mt++) {
        #pragma unroll
        for (int nt = 0; nt < 8; nt++) {
            #pragma unroll
            for (int c = 0; c < 4; c++) {
                int m = bm + wm + mt * 16 + g + ((c >> 1) ? 8 : 0);
                int n = bn + wn + nt * 8 + 2 * t4 + (c & 1);
                float v = acc[mt][nt][c] + bias[n];
                if (EPI == 0) {
                    out[(size_t)m * N_GL + n] = v;
                } else {
                    int b = m >> 11;
                    int t = m & (T_ - 1);
                    int which = n >> 9;     // 0=q, 1=k, 2=v
                    int r = n & 511;
                    int h = r >> 6, hd = r & 63;
                    int bh = b * H_ + h;
                    if (which == 0)
                        g_Qf[((size_t)bh * T_ + t) * HD_ + hd] = to_tf32(v * 0.125f);
                    else if (which == 1)
                        g_Kt[((size_t)bh * HD_ + hd) * T_ + t] = to_tf32(v);
                    else
                        g_Vt[((size_t)bh * HD_ + hd) * T_ + t] = to_tf32(v);
                }
            }
        }
    }
}

// ---------------------------------------------------------------------------
// Flash attention (causal), all-tf32 mma, cp.async double-buffered K/V.
// Grid: (qtile=16, bh=32). 128 threads = 4 warps; warp w owns 32 Q rows
// (mt=2 halves of 16). K/V fragments loaded ONCE per warp, fed to both
// m-halves -> smem crossbar bytes halved vs 8-warp version.
// ---------------------------------------------------------------------------
#define KBUF_F (64*72)     // floats per K buffer
#define VBUF_F (64*68)
#define ATTN_SMEM ((2*KBUF_F + 2*VBUF_F)*4)

__global__ __launch_bounds__(128, 2) void attn_mma()
{
    extern __shared__ float dynsmem[];
    float* Kbuf = dynsmem;                 // [2][64][72]
    float* Vbuf = dynsmem + 2 * KBUF_F;    // [2][64][68]

    int qt = 15 - blockIdx.x;     // big tiles first (load balance)
    int bh = blockIdx.y;
    int tid = threadIdx.x;
    int w = tid >> 5, lane = tid & 31;
    int g = lane >> 2, t4 = lane & 3;
    int q0 = qt * 128;

    int src_lo = (lane & ~3) | (t4 >> 1);
    int src_hi = src_lo + 2;
    bool odd = (t4 & 1) != 0;

    const float* Qp = g_Qf + (size_t)bh * T_ * HD_;
    const float* Kp = g_Kt + (size_t)bh * HD_ * T_;
    const float* Vp = g_Vt + (size_t)bh * HD_ * T_;

    unsigned k_smem = (unsigned)__cvta_generic_to_shared(Kbuf);
    unsigned v_smem = (unsigned)__cvta_generic_to_shared(Vbuf);

    int ld_row = tid >> 1;                 // 0..63
    int ld_c0  = (tid & 1) * 32;           // 0 or 32, + c*4 (c=0..7)

    // Q rows for this warp: mt half 0 -> r0, r0+8 ; half 1 -> r0+16, r0+24
    int r0 = q0 + w * 32 + g;
    float qa[2][8][4];
    #pragma unroll
    for (int mt = 0; mt < 2; mt++) {
        int rm = r0 + mt * 16;
        #pragma unroll
        for (int k = 0; k < 8; k++) {
            qa[mt][k][0] = Qp[(size_t)rm * HD_ + k * 8 + t4];
            qa[mt][k][1] = Qp[(size_t)(rm + 8) * HD_ + k * 8 + t4];
            qa[mt][k][2] = Qp[(size_t)rm * HD_ + k * 8 + t4 + 4];
            qa[mt][k][3] = Qp[(size_t)(rm + 8) * HD_ + k * 8 + t4 + 4];
        }
    }

    float O[2][8][4];
    #pragma unroll
    for (int mt = 0; mt < 2; mt++)
        #pragma unroll
        for (int n = 0; n < 8; n++)
            #pragma unroll
            for (int c = 0; c < 4; c++) O[mt][n][c] = 0.0f;
    float mx[2][2] = {{-1e30f, -1e30f}, {-1e30f, -1e30f}};
    float li[2][2] = {{0.0f, 0.0f}, {0.0f, 0.0f}};

    int nkt = 2 * (qt + 1);

    auto issue_tile = [&](int kt) {
        int bb = kt & 1;
        int j0 = kt * 64;
        unsigned kb = k_smem + (unsigned)(bb * KBUF_F) * 4;
        unsigned vb = v_smem + (unsigned)(bb * VBUF_F) * 4;
        #pragma unroll
        for (int c = 0; c < 8; c++) {
            int col = ld_c0 + c * 4;
            cp16(kb + (unsigned)(ld_row * 72 + col) * 4, Kp + (size_t)ld_row * T_ + j0 + col);
            cp16(vb + (unsigned)(ld_row * 68 + col) * 4, Vp + (size_t)ld_row * T_ + j0 + col);
        }
        asm volatile("cp.async.commit_group;");
    };

    issue_tile(0);

    for (int kt = 0; kt < nkt; kt++) {
        int bb = kt & 1;
        if (kt + 1 < nkt) {
            issue_tile(kt + 1);
            asm volatile("cp.async.wait_group 1;");
        } else {
            asm volatile("cp.async.wait_group 0;");
        }
        __syncthreads();

        const float* Kb = Kbuf + bb * KBUF_F;   // [d][j] stride 72
        const float* Vb = Vbuf + bb * VBUF_F;   // [dv][j] stride 68
        int j0 = kt * 64;

        // S = Q*K^T ; K-fragments read once, used by both m-halves
        float S[2][8][4];
        #pragma unroll
        for (int mt = 0; mt < 2; mt++)
            #pragma unroll
            for (int n = 0; n < 8; n++)
                #pragma unroll
                for (int c = 0; c < 4; c++) S[mt][n][c] = 0.0f;

        #pragma unroll
        for (int k = 0; k < 8; k++) {
            #pragma unroll
            for (int n = 0; n < 8; n++) {
                float b0 = Kb[(k * 8 + t4) * 72 + n * 8 + g];
                float b1 = Kb[(k * 8 + t4 + 4) * 72 + n * 8 + g];
                mma_tf32(S[0][n], qa[0][k], b0, b1);
                mma_tf32(S[1][n], qa[1][k], b0, b1);
            }
        }

        // Causal mask
        if (kt >= nkt - 2) {
            #pragma unroll
            for (int mt = 0; mt < 2; mt++) {
                int qi0 = r0 + mt * 16, qi1 = qi0 + 8;
                #pragma unroll
                for (int n = 0; n < 8; n++) {
                    int j = j0 + 8 * n + 2 * t4;
                    if (j     > qi0) S[mt][n][0] = -1e30f;
                    if (j + 1 > qi0) S[mt][n][1] = -1e30f;
                    if (j     > qi1) S[mt][n][2] = -1e30f;
                    if (j + 1 > qi1) S[mt][n][3] = -1e30f;
                }
            }
        }

        // Online softmax per m-half
        #pragma unroll
        for (int mt = 0; mt < 2; mt++) {
            float vmax0 = -1e30f, vmax1 = -1e30f;
            #pragma unroll
            for (int n = 0; n < 8; n++) {
                vmax0 = fmaxf(vmax0, fmaxf(S[mt][n][0], S[mt][n][1]));
                vmax1 = fmaxf(vmax1, fmaxf(S[mt][n][2], S[mt][n][3]));
            }
            vmax0 = fmaxf(vmax0, __shfl_xor_sync(0xffffffffu, vmax0, 1));
            vmax0 = fmaxf(vmax0, __shfl_xor_sync(0xffffffffu, vmax0, 2));
            vmax1 = fmaxf(vmax1, __shfl_xor_sync(0xffffffffu, vmax1, 1));
            vmax1 = fmaxf(vmax1, __shfl_xor_sync(0xffffffffu, vmax1, 2));

            float nm0 = fmaxf(mx[mt][0], vmax0);
            float nm1 = fmaxf(mx[mt][1], vmax1);
            float fac0 = __expf(mx[mt][0] - nm0);
            float fac1 = __expf(mx[mt][1] - nm1);
            mx[mt][0] = nm0; mx[mt][1] = nm1;

            float rs0 = 0.0f, rs1 = 0.0f;
            #pragma unroll
            for (int n = 0; n < 8; n++) {
                float p00 = to_tf32(__expf(S[mt][n][0] - nm0));
                float p01 = to_tf32(__expf(S[mt][n][1] - nm0));
                float p10 = to_tf32(__expf(S[mt][n][2] - nm1));
                float p11 = to_tf32(__expf(S[mt][n][3] - nm1));
                rs0 += p00 + p01;
                rs1 += p10 + p11;
                S[mt][n][0] = p00; S[mt][n][1] = p01;
                S[mt][n][2] = p10; S[mt][n][3] = p11;
            }
            rs0 += __shfl_xor_sync(0xffffffffu, rs0, 1);
            rs0 += __shfl_xor_sync(0xffffffffu, rs0, 2);
            rs1 += __shfl_xor_sync(0xffffffffu, rs1, 1);
            rs1 += __shfl_xor_sync(0xffffffffu, rs1, 2);
            li[mt][0] = li[mt][0] * fac0 + rs0;
            li[mt][1] = li[mt][1] * fac1 + rs1;

            #pragma unroll
            for (int n = 0; n < 8; n++) {
                O[mt][n][0] *= fac0; O[mt][n][1] *= fac0;
                O[mt][n][2] *= fac1; O[mt][n][3] *= fac1;
            }
        }

        // O += P*V ; V-fragments read once, used by both m-halves
        #pragma unroll
        for (int kk = 0; kk < 8; kk++) {
            float a2[2][4];
            #pragma unroll
            for (int mt = 0; mt < 2; mt++) {
                float p00 = S[mt][kk][0], p01 = S[mt][kk][1];
                float p10 = S[mt][kk][2], p11 = S[mt][kk][3];
                float x0 = __shfl_sync(0xffffffffu, p00, src_lo);
                float x1 = __shfl_sync(0xffffffffu, p01, src_lo);
                float y0 = __shfl_sync(0xffffffffu, p10, src_lo);
                float y1 = __shfl_sync(0xffffffffu, p11, src_lo);
                float z0 = __shfl_sync(0xffffffffu, p00, src_hi);
                float z1 = __shfl_sync(0xffffffffu, p01, src_hi);
                float u0 = __shfl_sync(0xffffffffu, p10, src_hi);
                float u1 = __shfl_sync(0xffffffffu, p11, src_hi);
                a2[mt][0] = odd ? x1 : x0;
                a2[mt][1] = odd ? y1 : y0;
                a2[mt][2] = odd ? z1 : z0;
                a2[mt][3] = odd ? u1 : u0;
            }
            #pragma unroll
            for (int n = 0; n < 8; n++) {
                float b0 = Vb[(8 * n + g) * 68 + 8 * kk + t4];
                float b1 = Vb[(8 * n + g) * 68 + 8 * kk + t4 + 4];
                mma_tf32(O[0][n], a2[0], b0, b1);
                mma_tf32(O[1][n], a2[1], b0, b1);
            }
        }
        __syncthreads();   // all reads of buffer bb done before refill
    }

    // Epilogue: normalize, tf32-round (feeds tf32 out-GEMM), write g_A
    int b = bh >> 3, h = bh & 7;
    #pragma unroll
    for (int mt = 0; mt < 2; mt++) {
        int rm = r0 + mt * 16;
        float inv0 = 1.0f / li[mt][0];
        float inv1 = 1.0f / li[mt][1];
        #pragma unroll
        for (int n = 0; n < 8; n++) {
            int dv = 8 * n + 2 * t4;
            float2 v0 = make_float2(to_tf32(O[mt][n][0] * inv0), to_tf32(O[mt][n][1] * inv0));
            float2 v1 = make_float2(to_tf32(O[mt][n][2] * inv1), to_tf32(O[mt][n][3] * inv1));
            *(float2*)&g_A[((size_t)b * T_ + rm)     * D_ + h * HD_ + dv] = v0;
            *(float2*)&g_A[((size_t)b * T_ + rm + 8) * D_ + h * HD_ + dv] = v1;
        }
    }
}

// ---------------------------------------------------------------------------
extern "C" void kernel_launch(void* const* d_in, const int* in_sizes, int n_in,
                              void* d_out, int out_size)
{
    const float* x     = (const float*)d_in[0];   // [4,2048,512]
    const float* W_qkv = (const float*)d_in[1];   // [512,1536]
    const float* b_qkv = (const float*)d_in[2];   // [1536]
    const float* W_out = (const float*)d_in[3];   // [512,512]
    const float* b_out = (const float*)d_in[4];   // [512]
    float* out = (float*)d_out;                   // [4,2048,512]

    cudaFuncSetAttribute(attn_mma, cudaFuncAttributeMaxDynamicSharedMemorySize, ATTN_SMEM);

    gemm_tf32<1536, 1, false><<<dim3(12, 64), 128>>>(x, W_qkv, b_qkv, nullptr);
    attn_mma<<<dim3(16, 32), 128, ATTN_SMEM>>>();
    gemm_tf32<512, 0, true><<<dim3(4, 64), 128>>>(nullptr, W_out, b_out, out);
}

// round 8
// speedup vs baseline: 1.1912x; 1.1912x over previous
#include <cuda_runtime.h>
#include <cuda_bf16.h>

#define B_  4
#define T_  2048
#define D_  512
#define H_  8
#define HD_ 64
#define BH_ (B_*H_)   // 32

// Scratch (allocation-free rule: __device__ globals)
__device__ __align__(16) float g_Qf[BH_*T_*HD_];   // [b,h,t,hd] tf32, pre-scaled 0.125
__device__ __align__(16) float g_Kt[BH_*HD_*T_];   // [b,h,hd,t] tf32 (transposed)
__device__ __align__(16) float g_Vt[BH_*HD_*T_];   // [b,h,dv,t] tf32 (transposed)
__device__ __align__(16) float g_A [B_*T_*D_];     // attention out [b,t,D], tf32-rounded

__device__ __forceinline__ float to_tf32(float x) {
    float r;
    asm("cvt.rna.tf32.f32 %0, %1;" : "=f"(r) : "f"(x));
    return r;
}

__device__ __forceinline__ void mma_tf32(float* c, const float* a, float b0, float b1) {
    asm volatile(
        "mma.sync.aligned.m16n8k8.row.col.f32.tf32.tf32.f32 "
        "{%0,%1,%2,%3},{%4,%5,%6,%7},{%8,%9},{%0,%1,%2,%3};"
        : "+f"(c[0]), "+f"(c[1]), "+f"(c[2]), "+f"(c[3])
        : "r"(__float_as_uint(a[0])), "r"(__float_as_uint(a[1])),
          "r"(__float_as_uint(a[2])), "r"(__float_as_uint(a[3])),
          "r"(__float_as_uint(b0)), "r"(__float_as_uint(b1)));
}

__device__ __forceinline__ void cp16(unsigned dst, const void* src) {
    asm volatile("cp.async.cg.shared.global [%0], [%1], 16;" :: "r"(dst), "l"(src));
}

// ===========================================================================
// tf32 mma GEMM: C[128x128] = A[128x512] * B[512x128] (+bias).
// 256 threads = 8 warps (4m x 2n), warp tile 32x64 (R6 sweet spot).
// 3-stage cp.async ring, k-tile 16, ONE __syncthreads per k-tile.
// EPI: 0 = plain store + bias ; 1 = qkv scatter epilogue.
// A_GA: read A from device-global g_A inside device code (a __device__
//       symbol passed as a host-side kernel arg resolves to the host shadow).
// ===========================================================================
#define GA_F (128*20)    // floats per A stage
#define GB_F (16*136)    // floats per B stage
#define GEMM_SMEM ((3*GA_F + 3*GB_F)*4)   // 56832 B

template<int N_GL, int EPI, bool A_GA>
__global__ __launch_bounds__(256, 2) void gemm_tf32(
    const float* __restrict__ A_in,
    const float* __restrict__ B_gl,
    const float* __restrict__ bias,
    float* __restrict__ out)
{
    const int K = 512;
    const float* A_gl = A_GA ? (const float*)g_A : A_in;

    extern __shared__ float smem[];
    float* Abuf = smem;               // [3][128][20]  stride 20 (== 4 mod 32)
    float* Bbuf = smem + 3 * GA_F;    // [3][16][136]  stride 136 (== 8 mod 32)

    int bm = blockIdx.y * 128, bn = blockIdx.x * 128;
    int tid = threadIdx.x;
    int w = tid >> 5, lane = tid & 31, g = lane >> 2, t4 = lane & 3;
    int wm = (w >> 1) * 32, wn = (w & 1) * 64;

    unsigned sA = (unsigned)__cvta_generic_to_shared(Abuf);
    unsigned sB = (unsigned)__cvta_generic_to_shared(Bbuf);

    int a_row = tid >> 1, a_kc = (tid & 1) * 8;     // A: [row][a_kc..a_kc+7]
    int b_row = tid >> 4, b_cc = (tid & 15) * 8;    // B: [row][b_cc..b_cc+7]

    auto issue_tile = [&](int kt) {
        int buf = kt - (kt / 3) * 3;
        int k0 = kt * 16;
        const float* asrc = A_gl + (size_t)(bm + a_row) * K + k0 + a_kc;
        unsigned da = sA + (unsigned)(buf * GA_F + a_row * 20 + a_kc) * 4;
        cp16(da, asrc);
        cp16(da + 16, asrc + 4);
        const float* bsrc = B_gl + (size_t)(k0 + b_row) * N_GL + bn + b_cc;
        unsigned db = sB + (unsigned)(buf * GB_F + b_row * 136 + b_cc) * 4;
        cp16(db, bsrc);
        cp16(db + 16, bsrc + 4);
        asm volatile("cp.async.commit_group;");
    };

    float acc[2][8][4];
    #pragma unroll
    for (int mt = 0; mt < 2; mt++)
        #pragma unroll
        for (int nt = 0; nt < 8; nt++)
            #pragma unroll
            for (int c = 0; c < 4; c++) acc[mt][nt][c] = 0.0f;

    issue_tile(0);
    issue_tile(1);

    #pragma unroll 1
    for (int kt = 0; kt < 32; kt++) {
        int buf = kt - (kt / 3) * 3;
        if (kt < 31) {
            asm volatile("cp.async.wait_group 1;");
        } else {
            asm volatile("cp.async.wait_group 0;");
        }
        __syncthreads();   // also fences reads of buf (kt+2)%3 from iter kt-1
        if (kt + 2 < 32) issue_tile(kt + 2);

        const float* As = Abuf + buf * GA_F;   // [128][20]
        const float* Bs = Bbuf + buf * GB_F;   // [16][136]

        #pragma unroll
        for (int ks = 0; ks < 2; ks++) {
            int k0 = ks * 8;
            float af[2][4];
            #pragma unroll
            for (int mt = 0; mt < 2; mt++) {
                af[mt][0] = to_tf32(As[(wm + mt * 16 + g) * 20 + k0 + t4]);
                af[mt][1] = to_tf32(As[(wm + mt * 16 + g + 8) * 20 + k0 + t4]);
                af[mt][2] = to_tf32(As[(wm + mt * 16 + g) * 20 + k0 + t4 + 4]);
                af[mt][3] = to_tf32(As[(wm + mt * 16 + g + 8) * 20 + k0 + t4 + 4]);
            }
            #pragma unroll
            for (int nt = 0; nt < 8; nt++) {
                float b0 = to_tf32(Bs[(k0 + t4) * 136 + wn + nt * 8 + g]);
                float b1 = to_tf32(Bs[(k0 + t4 + 4) * 136 + wn + nt * 8 + g]);
                mma_tf32(acc[0][nt], af[0], b0, b1);
                mma_tf32(acc[1][nt], af[1], b0, b1);
            }
        }
    }

    // Epilogue
    #pragma unroll
    for (int mt = 0; mt < 2; mt++) {
        #pragma unroll
        for (int nt = 0; nt < 8; nt++) {
            #pragma unroll
            for (int c = 0; c < 4; c++) {
                int m = bm + wm + mt * 16 + g + ((c >> 1) ? 8 : 0);
                int n = bn + wn + nt * 8 + 2 * t4 + (c & 1);
                float v = acc[mt][nt][c] + bias[n];
                if (EPI == 0) {
                    out[(size_t)m * N_GL + n] = v;
                } else {
                    int b = m >> 11;
                    int t = m & (T_ - 1);
                    int which = n >> 9;     // 0=q, 1=k, 2=v
                    int r = n & 511;
                    int h = r >> 6, hd = r & 63;
                    int bh = b * H_ + h;
                    if (which == 0)
                        g_Qf[((size_t)bh * T_ + t) * HD_ + hd] = to_tf32(v * 0.125f);
                    else if (which == 1)
                        g_Kt[((size_t)bh * HD_ + hd) * T_ + t] = to_tf32(v);
                    else
                        g_Vt[((size_t)bh * HD_ + hd) * T_ + t] = to_tf32(v);
                }
            }
        }
    }
}

// ---------------------------------------------------------------------------
// Flash attention (causal), all-tf32 mma, 3-stage cp.async ring for K/V.
// Grid: (qtile=16, bh=32). 256 threads = 8 warps; warp w owns Q rows
// [q0+16w, q0+16w+16). KV tiles of 64. ONE __syncthreads per kv-tile.
// ---------------------------------------------------------------------------
#define KBUF_F (64*72)     // floats per K stage
#define VBUF_F (64*68)
#define ATTN_SMEM ((3*KBUF_F + 3*VBUF_F)*4)   // 107520 B

__global__ __launch_bounds__(256, 2) void attn_mma()
{
    extern __shared__ float dynsmem[];
    float* Kbuf = dynsmem;                 // [3][64][72]
    float* Vbuf = dynsmem + 3 * KBUF_F;    // [3][64][68]

    int qt = 15 - blockIdx.x;     // big tiles first (load balance)
    int bh = blockIdx.y;
    int tid = threadIdx.x;
    int w = tid >> 5, lane = tid & 31;
    int g = lane >> 2, t4 = lane & 3;
    int q0 = qt * 128;

    int src_lo = (lane & ~3) | (t4 >> 1);
    int src_hi = src_lo + 2;
    bool odd = (t4 & 1) != 0;

    const float* Qp = g_Qf + (size_t)bh * T_ * HD_;
    const float* Kp = g_Kt + (size_t)bh * HD_ * T_;
    const float* Vp = g_Vt + (size_t)bh * HD_ * T_;

    unsigned k_smem = (unsigned)__cvta_generic_to_shared(Kbuf);
    unsigned v_smem = (unsigned)__cvta_generic_to_shared(Vbuf);

    int ld_row = tid >> 4;                 // 0..15 (+16 per i)
    int ld_c4  = (tid & 15) << 2;          // 0..60

    int r0 = q0 + w * 16 + g;
    float qa[8][4];
    #pragma unroll
    for (int k = 0; k < 8; k++) {
        qa[k][0] = Qp[(size_t)r0 * HD_ + k * 8 + t4];
        qa[k][1] = Qp[(size_t)(r0 + 8) * HD_ + k * 8 + t4];
        qa[k][2] = Qp[(size_t)r0 * HD_ + k * 8 + t4 + 4];
        qa[k][3] = Qp[(size_t)(r0 + 8) * HD_ + k * 8 + t4 + 4];
    }

    float O[8][4];
    #pragma unroll
    for (int n = 0; n < 8; n++)
        #pragma unroll
        for (int c = 0; c < 4; c++) O[n][c] = 0.0f;
    float m0 = -1e30f, m1 = -1e30f, l0 = 0.0f, l1 = 0.0f;

    int nkt = 2 * (qt + 1);   // always >= 2

    auto issue_tile = [&](int kt) {
        int bb = kt - (kt / 3) * 3;
        int j0 = kt * 64;
        unsigned kb = k_smem + (unsigned)(bb * KBUF_F) * 4;
        unsigned vb = v_smem + (unsigned)(bb * VBUF_F) * 4;
        #pragma unroll
        for (int i = 0; i < 4; i++) {
            int row = ld_row + i * 16;
            cp16(kb + (unsigned)(row * 72 + ld_c4) * 4, Kp + (size_t)row * T_ + j0 + ld_c4);
            cp16(vb + (unsigned)(row * 68 + ld_c4) * 4, Vp + (size_t)row * T_ + j0 + ld_c4);
        }
        asm volatile("cp.async.commit_group;");
    };

    issue_tile(0);
    issue_tile(1);

    for (int kt = 0; kt < nkt; kt++) {
        int bb = kt - (kt / 3) * 3;
        if (kt < nkt - 1) {
            asm volatile("cp.async.wait_group 1;");
        } else {
            asm volatile("cp.async.wait_group 0;");
        }
        __syncthreads();   // fences reads of buf (kt+2)%3 from iter kt-1
        if (kt + 2 < nkt) issue_tile(kt + 2);

        const float* Kb = Kbuf + bb * KBUF_F;   // [d][j] stride 72
        const float* Vb = Vbuf + bb * VBUF_F;   // [dv][j] stride 68
        int j0 = kt * 64;

        float S[8][4];
        #pragma unroll
        for (int n = 0; n < 8; n++)
            #pragma unroll
            for (int c = 0; c < 4; c++) S[n][c] = 0.0f;

        #pragma unroll
        for (int k = 0; k < 8; k++) {
            #pragma unroll
            for (int n = 0; n < 8; n++) {
                float b0 = Kb[(k * 8 + t4) * 72 + n * 8 + g];
                float b1 = Kb[(k * 8 + t4 + 4) * 72 + n * 8 + g];
                mma_tf32(S[n], qa[k], b0, b1);
            }
        }

        if (kt >= nkt - 2) {
            int qi0 = r0, qi1 = r0 + 8;
            #pragma unroll
            for (int n = 0; n < 8; n++) {
                int j = j0 + 8 * n + 2 * t4;
                if (j     > qi0) S[n][0] = -1e30f;
                if (j + 1 > qi0) S[n][1] = -1e30f;
                if (j     > qi1) S[n][2] = -1e30f;
                if (j + 1 > qi1) S[n][3] = -1e30f;
            }
        }

        float vmax0 = -1e30f, vmax1 = -1e30f;
        #pragma unroll
        for (int n = 0; n < 8; n++) {
            vmax0 = fmaxf(vmax0, fmaxf(S[n][0], S[n][1]));
            vmax1 = fmaxf(vmax1, fmaxf(S[n][2], S[n][3]));
        }
        vmax0 = fmaxf(vmax0, __shfl_xor_sync(0xffffffffu, vmax0, 1));
        vmax0 = fmaxf(vmax0, __shfl_xor_sync(0xffffffffu, vmax0, 2));
        vmax1 = fmaxf(vmax1, __shfl_xor_sync(0xffffffffu, vmax1, 1));
        vmax1 = fmaxf(vmax1, __shfl_xor_sync(0xffffffffu, vmax1, 2));

        float nm0 = fmaxf(m0, vmax0);
        float nm1 = fmaxf(m1, vmax1);
        float fac0 = __expf(m0 - nm0);
        float fac1 = __expf(m1 - nm1);
        m0 = nm0; m1 = nm1;

        float rs0 = 0.0f, rs1 = 0.0f;
        #pragma unroll
        for (int n = 0; n < 8; n++) {
            float p00 = to_tf32(__expf(S[n][0] - nm0));
            float p01 = to_tf32(__expf(S[n][1] - nm0));
            float p10 = to_tf32(__expf(S[n][2] - nm1));
            float p11 = to_tf32(__expf(S[n][3] - nm1));
            rs0 += p00 + p01;
            rs1 += p10 + p11;
            S[n][0] = p00; S[n][1] = p01; S[n][2] = p10; S[n][3] = p11;
        }
        rs0 += __shfl_xor_sync(0xffffffffu, rs0, 1);
        rs0 += __shfl_xor_sync(0xffffffffu, rs0, 2);
        rs1 += __shfl_xor_sync(0xffffffffu, rs1, 1);
        rs1 += __shfl_xor_sync(0xffffffffu, rs1, 2);
        l0 = l0 * fac0 + rs0;
        l1 = l1 * fac1 + rs1;

        #pragma unroll
        for (int n = 0; n < 8; n++) {
            O[n][0] *= fac0; O[n][1] *= fac0;
            O[n][2] *= fac1; O[n][3] *= fac1;
        }

        #pragma unroll
        for (int kk = 0; kk < 8; kk++) {
            float p00 = S[kk][0], p01 = S[kk][1];
            float p10 = S[kk][2], p11 = S[kk][3];
            float x0 = __shfl_sync(0xffffffffu, p00, src_lo);
            float x1 = __shfl_sync(0xffffffffu, p01, src_lo);
            float y0 = __shfl_sync(0xffffffffu, p10, src_lo);
            float y1 = __shfl_sync(0xffffffffu, p11, src_lo);
            float z0 = __shfl_sync(0xffffffffu, p00, src_hi);
            float z1 = __shfl_sync(0xffffffffu, p01, src_hi);
            float u0 = __shfl_sync(0xffffffffu, p10, src_hi);
            float u1 = __shfl_sync(0xffffffffu, p11, src_hi);
            float a[4];
            a[0] = odd ? x1 : x0;
            a[1] = odd ? y1 : y0;
            a[2] = odd ? z1 : z0;
            a[3] = odd ? u1 : u0;
            #pragma unroll
            for (int n = 0; n < 8; n++) {
                float b0 = Vb[(8 * n + g) * 68 + 8 * kk + t4];
                float b1 = Vb[(8 * n + g) * 68 + 8 * kk + t4 + 4];
                mma_tf32(O[n], a, b0, b1);
            }
        }
    }

    // Epilogue: normalize, tf32-round (feeds tf32 out-GEMM), write g_A
    int b = bh >> 3, h = bh & 7;
    float inv0 = 1.0f / l0;
    float inv1 = 1.0f / l1;
    #pragma unroll
    for (int n = 0; n < 8; n++) {
        int dv = 8 * n + 2 * t4;
        float2 v0 = make_float2(to_tf32(O[n][0] * inv0), to_tf32(O[n][1] * inv0));
        float2 v1 = make_float2(to_tf32(O[n][2] * inv1), to_tf32(O[n][3] * inv1));
        *(float2*)&g_A[((size_t)b * T_ + r0)     * D_ + h * HD_ + dv] = v0;
        *(float2*)&g_A[((size_t)b * T_ + r0 + 8) * D_ + h * HD_ + dv] = v1;
    }
}

// ---------------------------------------------------------------------------
extern "C" void kernel_launch(void* const* d_in, const int* in_sizes, int n_in,
                              void* d_out, int out_size)
{
    const float* x     = (const float*)d_in[0];   // [4,2048,512]
    const float* W_qkv = (const float*)d_in[1];   // [512,1536]
    const float* b_qkv = (const float*)d_in[2];   // [1536]
    const float* W_out = (const float*)d_in[3];   // [512,512]
    const float* b_out = (const float*)d_in[4];   // [512]
    float* out = (float*)d_out;                   // [4,2048,512]

    cudaFuncSetAttribute(gemm_tf32<1536, 1, false>,
                         cudaFuncAttributeMaxDynamicSharedMemorySize, GEMM_SMEM);
    cudaFuncSetAttribute(gemm_tf32<512, 0, true>,
                         cudaFuncAttributeMaxDynamicSharedMemorySize, GEMM_SMEM);
    cudaFuncSetAttribute(attn_mma, cudaFuncAttributeMaxDynamicSharedMemorySize, ATTN_SMEM);

    gemm_tf32<1536, 1, false><<<dim3(12, 64), 256, GEMM_SMEM>>>(x, W_qkv, b_qkv, nullptr);
    attn_mma<<<dim3(16, 32), 256, ATTN_SMEM>>>();
    gemm_tf32<512, 0, true><<<dim3(4, 64), 256, GEMM_SMEM>>>(nullptr, W_out, b_out, out);
}

// round 9
// speedup vs baseline: 2.0587x; 1.7283x over previous
#include <cuda_runtime.h>
#include <cuda_fp16.h>

#define B_  4
#define T_  2048
#define D_  512
#define H_  8
#define HD_ 64
#define BH_ (B_*H_)   // 32

// Scratch (allocation-free rule: __device__ globals). All fp16.
__device__ __align__(16) __half g_Xh   [8192*512];   // x, fp16
__device__ __align__(16) __half g_WqkvT[1536*512];   // W_qkv^T  [n][k]
__device__ __align__(16) __half g_WoutT[512*512];    // W_out^T  [n][k]
__device__ __align__(16) __half g_Qh   [BH_*T_*HD_]; // [bh][t][d], pre-scaled 0.125
__device__ __align__(16) __half g_Kh   [BH_*T_*HD_]; // [bh][t][d]
__device__ __align__(16) __half g_Vh   [BH_*HD_*T_]; // [bh][dv][t]
__device__ __align__(16) __half g_Ah   [8192*512];   // attention out, fp16

__device__ __forceinline__ unsigned pack_h2(float x, float y) {
    __half2 h = __floats2half2_rn(x, y);
    return *(unsigned*)&h;
}
__device__ __forceinline__ float2 unpack_h2(unsigned u) {
    __half2 h = *(__half2*)&u;
    return __half22float2(h);
}

__device__ __forceinline__ void mma_f16(float* c, const unsigned* a, unsigned b0, unsigned b1) {
    asm volatile(
        "mma.sync.aligned.m16n8k16.row.col.f32.f16.f16.f32 "
        "{%0,%1,%2,%3},{%4,%5,%6,%7},{%8,%9},{%0,%1,%2,%3};"
        : "+f"(c[0]), "+f"(c[1]), "+f"(c[2]), "+f"(c[3])
        : "r"(a[0]), "r"(a[1]), "r"(a[2]), "r"(a[3]), "r"(b0), "r"(b1));
}

__device__ __forceinline__ void cp16(unsigned dst, const void* src) {
    asm volatile("cp.async.cg.shared.global [%0], [%1], 16;" :: "r"(dst), "l"(src));
}

// ---------------------------------------------------------------------------
// Pre-convert kernels
// ---------------------------------------------------------------------------
__global__ void conv_x_f16(const float* __restrict__ in)   // 8192*512 elements
{
    int i = (blockIdx.x * 256 + threadIdx.x) * 4;
    float4 v = *(const float4*)(in + i);
    __half2* o = (__half2*)(g_Xh + i);
    o[0] = __floats2half2_rn(v.x, v.y);
    o[1] = __floats2half2_rn(v.z, v.w);
}

template<int SEL>   // 0: W_qkv -> g_WqkvT ; 1: W_out -> g_WoutT
__global__ void transpose_w(const float* __restrict__ in, int R, int C)
{
    __half* outp = SEL ? (__half*)g_WoutT : (__half*)g_WqkvT;
    __shared__ float tile[32][33];
    int c0 = blockIdx.x * 32, r0 = blockIdx.y * 32;
    for (int i = threadIdx.y; i < 32; i += 8)
        tile[i][threadIdx.x] = in[(size_t)(r0 + i) * C + c0 + threadIdx.x];
    __syncthreads();
    for (int i = threadIdx.y; i < 32; i += 8)
        outp[(size_t)(c0 + i) * R + r0 + threadIdx.x] = __float2half(tile[threadIdx.x][i]);
}

// ===========================================================================
// fp16 mma GEMM: C[128x128] = A[128x512] * B^T (+bias).
// A [M][512] fp16, B [N][512] fp16 (pre-transposed). 256 thr = 8 warps
// (4m x 2n), warp tile 32x64, k-tile 32 (2 k16 steps), 3-stage cp.async ring.
// Smem rows 40 halves: fragment banks (20g + t4) mod 32 all distinct.
// ===========================================================================
#define AST_H (128*40)    // halves per stage
#define GEMM_SMEM (6*AST_H*2)   // 61440 B

template<int N_GL, int EPI, int ASRC, int BSRC>
__global__ __launch_bounds__(256, 2) void gemm_f16(
    const float* __restrict__ bias,
    float* __restrict__ out)
{
    const __half* A_gl = (ASRC == 0) ? (const __half*)g_Xh    : (const __half*)g_Ah;
    const __half* B_gl = (BSRC == 0) ? (const __half*)g_WqkvT : (const __half*)g_WoutT;

    extern __shared__ char dsm[];
    __half* Abuf = (__half*)dsm;            // [3][128][40]
    __half* Bbuf = (__half*)dsm + 3 * AST_H;

    int bm = blockIdx.y * 128, bn = blockIdx.x * 128;
    int tid = threadIdx.x;
    int w = tid >> 5, lane = tid & 31, g = lane >> 2, t4 = lane & 3;
    int wm = (w >> 1) * 32, wn = (w & 1) * 64;

    unsigned sA = (unsigned)__cvta_generic_to_shared(Abuf);
    unsigned sB = (unsigned)__cvta_generic_to_shared(Bbuf);

    int a_row = tid >> 1;             // 0..127 (A m-row and B n-row)
    int a_hc  = (tid & 1) * 16;       // halves 0 or 16

    auto issue_tile = [&](int kt) {
        int buf = kt - (kt / 3) * 3;
        int k0 = kt * 32;
        const __half* asrc = A_gl + (size_t)(bm + a_row) * 512 + k0 + a_hc;
        unsigned da = sA + (unsigned)(buf * AST_H + a_row * 40 + a_hc) * 2;
        cp16(da, asrc); cp16(da + 16, asrc + 8);
        const __half* bsrc = B_gl + (size_t)(bn + a_row) * 512 + k0 + a_hc;
        unsigned db = sB + (unsigned)(buf * AST_H + a_row * 40 + a_hc) * 2;
        cp16(db, bsrc); cp16(db + 16, bsrc + 8);
        asm volatile("cp.async.commit_group;");
    };

    float acc[2][8][4];
    #pragma unroll
    for (int mt = 0; mt < 2; mt++)
        #pragma unroll
        for (int nt = 0; nt < 8; nt++)
            #pragma unroll
            for (int c = 0; c < 4; c++) acc[mt][nt][c] = 0.0f;

    issue_tile(0);
    issue_tile(1);

    #pragma unroll 1
    for (int kt = 0; kt < 16; kt++) {
        int buf = kt - (kt / 3) * 3;
        if (kt < 15) {
            asm volatile("cp.async.wait_group 1;");
        } else {
            asm volatile("cp.async.wait_group 0;");
        }
        __syncthreads();
        if (kt + 2 < 16) issue_tile(kt + 2);

        const __half* As = Abuf + buf * AST_H;
        const __half* Bs = Bbuf + buf * AST_H;

        #pragma unroll
        for (int ks = 0; ks < 2; ks++) {
            int k0 = ks * 16 + 2 * t4;
            unsigned af[2][4];
            #pragma unroll
            for (int mt = 0; mt < 2; mt++) {
                int base = (wm + mt * 16 + g) * 40 + k0;
                af[mt][0] = *(const unsigned*)&As[base];
                af[mt][1] = *(const unsigned*)&As[base + 8 * 40];
                af[mt][2] = *(const unsigned*)&As[base + 8];
                af[mt][3] = *(const unsigned*)&As[base + 8 * 40 + 8];
            }
            #pragma unroll
            for (int nt = 0; nt < 8; nt++) {
                int bbase = (wn + nt * 8 + g) * 40 + k0;
                unsigned b0 = *(const unsigned*)&Bs[bbase];
                unsigned b1 = *(const unsigned*)&Bs[bbase + 8];
                mma_f16(acc[0][nt], af[0], b0, b1);
                mma_f16(acc[1][nt], af[1], b0, b1);
            }
        }
    }

    // Epilogue
    #pragma unroll
    for (int mt = 0; mt < 2; mt++) {
        #pragma unroll
        for (int nt = 0; nt < 8; nt++) {
            #pragma unroll
            for (int c = 0; c < 4; c++) {
                int m = bm + wm + mt * 16 + g + ((c >> 1) ? 8 : 0);
                int n = bn + wn + nt * 8 + 2 * t4 + (c & 1);
                float v = acc[mt][nt][c] + bias[n];
                if (EPI == 0) {
                    out[(size_t)m * N_GL + n] = v;
                } else {
                    int b = m >> 11;
                    int t = m & (T_ - 1);
                    int which = n >> 9;     // 0=q, 1=k, 2=v
                    int r = n & 511;
                    int h = r >> 6, hd = r & 63;
                    int bh = b * H_ + h;
                    if (which == 0)
                        g_Qh[((size_t)bh * T_ + t) * HD_ + hd] = __float2half(v * 0.125f);
                    else if (which == 1)
                        g_Kh[((size_t)bh * T_ + t) * HD_ + hd] = __float2half(v);
                    else
                        g_Vh[((size_t)bh * HD_ + hd) * T_ + t] = __float2half(v);
                }
            }
        }
    }
}

// ---------------------------------------------------------------------------
// Flash attention (causal), fp16 m16n8k16 mma, cp.async double-buffered K/V.
// Grid: (qtile=16, bh=32). 256 threads = 8 warps; warp w owns Q rows
// [q0+16w, q0+16w+16). KV tiles of 64. K smem [j][d], V smem [dv][j],
// both stride 72 halves (banks 4g+t4 distinct). P chains register->A-frag
// (no shuffles). l summed from fp16-ROUNDED P for consistency.
// ---------------------------------------------------------------------------
#define KST_H (64*72)     // halves per K (or V) stage
#define ATTN_SMEM (4*KST_H*2)   // 36864 B

__global__ __launch_bounds__(256, 2) void attn_f16()
{
    extern __shared__ char dsm[];
    __half* Kbuf = (__half*)dsm;             // [2][64][72]
    __half* Vbuf = (__half*)dsm + 2 * KST_H; // [2][64][72]

    int qt = 15 - blockIdx.x;     // big tiles first (load balance)
    int bh = blockIdx.y;
    int tid = threadIdx.x;
    int w = tid >> 5, lane = tid & 31;
    int g = lane >> 2, t4 = lane & 3;
    int q0 = qt * 128;

    const __half* Qp = g_Qh + (size_t)bh * T_ * HD_;
    const __half* Kp = g_Kh + (size_t)bh * T_ * HD_;
    const __half* Vp = g_Vh + (size_t)bh * HD_ * T_;

    unsigned k_smem = (unsigned)__cvta_generic_to_shared(Kbuf);
    unsigned v_smem = (unsigned)__cvta_generic_to_shared(Vbuf);

    int ld_row = tid >> 2;                // 0..63
    int ld_hc  = (tid & 3) * 16;          // halves 0,16,32,48

    int r0 = q0 + w * 16 + g;

    // Q fragments straight from gmem: 4 k16 steps x 4 half2 regs
    unsigned qa[4][4];
    #pragma unroll
    for (int ks = 0; ks < 4; ks++) {
        int k0 = ks * 16 + 2 * t4;
        qa[ks][0] = *(const unsigned*)&Qp[(size_t)r0 * HD_ + k0];
        qa[ks][1] = *(const unsigned*)&Qp[(size_t)(r0 + 8) * HD_ + k0];
        qa[ks][2] = *(const unsigned*)&Qp[(size_t)r0 * HD_ + k0 + 8];
        qa[ks][3] = *(const unsigned*)&Qp[(size_t)(r0 + 8) * HD_ + k0 + 8];
    }

    float O[8][4];
    #pragma unroll
    for (int n = 0; n < 8; n++)
        #pragma unroll
        for (int c = 0; c < 4; c++) O[n][c] = 0.0f;
    float m0 = -1e30f, m1 = -1e30f, l0 = 0.0f, l1 = 0.0f;

    int nkt = 2 * (qt + 1);

    auto issue_tile = [&](int kt) {
        int bb = kt & 1;
        int j0 = kt * 64;
        unsigned kb = k_smem + (unsigned)(bb * KST_H) * 2;
        unsigned vb = v_smem + (unsigned)(bb * KST_H) * 2;
        // K tile: rows j (token), 64 halves of d each
        cp16(kb + (unsigned)(ld_row * 72 + ld_hc) * 2,
             Kp + (size_t)(j0 + ld_row) * HD_ + ld_hc);
        cp16(kb + (unsigned)(ld_row * 72 + ld_hc + 8) * 2,
             Kp + (size_t)(j0 + ld_row) * HD_ + ld_hc + 8);
        // V tile: rows dv, 64 halves of j each
        cp16(vb + (unsigned)(ld_row * 72 + ld_hc) * 2,
             Vp + (size_t)ld_row * T_ + j0 + ld_hc);
        cp16(vb + (unsigned)(ld_row * 72 + ld_hc + 8) * 2,
             Vp + (size_t)ld_row * T_ + j0 + ld_hc + 8);
        asm volatile("cp.async.commit_group;");
    };

    issue_tile(0);

    for (int kt = 0; kt < nkt; kt++) {
        int bb = kt & 1;
        if (kt + 1 < nkt) {
            issue_tile(kt + 1);
            asm volatile("cp.async.wait_group 1;");
        } else {
            asm volatile("cp.async.wait_group 0;");
        }
        __syncthreads();

        const __half* Kb = Kbuf + bb * KST_H;   // [j][d] stride 72
        const __half* Vb = Vbuf + bb * KST_H;   // [dv][j] stride 72
        int j0 = kt * 64;

        // S = Q*K^T : 4 k16 steps x 8 n-tiles
        float S[8][4];
        #pragma unroll
        for (int n = 0; n < 8; n++)
            #pragma unroll
            for (int c = 0; c < 4; c++) S[n][c] = 0.0f;

        #pragma unroll
        for (int ks = 0; ks < 4; ks++) {
            int k0 = ks * 16 + 2 * t4;
            #pragma unroll
            for (int n = 0; n < 8; n++) {
                int base = (8 * n + g) * 72 + k0;
                unsigned b0 = *(const unsigned*)&Kb[base];
                unsigned b1 = *(const unsigned*)&Kb[base + 8];
                mma_f16(S[n], qa[ks], b0, b1);
            }
        }

        // Causal mask (only last two tiles can straddle the diagonal)
        if (kt >= nkt - 2) {
            int qi0 = r0, qi1 = r0 + 8;
            #pragma unroll
            for (int n = 0; n < 8; n++) {
                int j = j0 + 8 * n + 2 * t4;
                if (j     > qi0) S[n][0] = -1e30f;
                if (j + 1 > qi0) S[n][1] = -1e30f;
                if (j     > qi1) S[n][2] = -1e30f;
                if (j + 1 > qi1) S[n][3] = -1e30f;
            }
        }

        // Online softmax (rows r0 and r0+8; quad lanes share a row)
        float vmax0 = -1e30f, vmax1 = -1e30f;
        #pragma unroll
        for (int n = 0; n < 8; n++) {
            vmax0 = fmaxf(vmax0, fmaxf(S[n][0], S[n][1]));
            vmax1 = fmaxf(vmax1, fmaxf(S[n][2], S[n][3]));
        }
        vmax0 = fmaxf(vmax0, __shfl_xor_sync(0xffffffffu, vmax0, 1));
        vmax0 = fmaxf(vmax0, __shfl_xor_sync(0xffffffffu, vmax0, 2));
        vmax1 = fmaxf(vmax1, __shfl_xor_sync(0xffffffffu, vmax1, 1));
        vmax1 = fmaxf(vmax1, __shfl_xor_sync(0xffffffffu, vmax1, 2));

        float nm0 = fmaxf(m0, vmax0);
        float nm1 = fmaxf(m1, vmax1);
        float fac0 = __expf(m0 - nm0);
        float fac1 = __expf(m1 - nm1);
        m0 = nm0; m1 = nm1;

        // P = exp(S-m) -> fp16 A-fragments; l accumulates the ROUNDED p
        unsigned pa[8][2];
        float rs0 = 0.0f, rs1 = 0.0f;
        #pragma unroll
        for (int n = 0; n < 8; n++) {
            unsigned u0 = pack_h2(__expf(S[n][0] - nm0), __expf(S[n][1] - nm0));
            unsigned u1 = pack_h2(__expf(S[n][2] - nm1), __expf(S[n][3] - nm1));
            pa[n][0] = u0; pa[n][1] = u1;
            float2 f0 = unpack_h2(u0);
            float2 f1 = unpack_h2(u1);
            rs0 += f0.x + f0.y;
            rs1 += f1.x + f1.y;
        }
        rs0 += __shfl_xor_sync(0xffffffffu, rs0, 1);
        rs0 += __shfl_xor_sync(0xffffffffu, rs0, 2);
        rs1 += __shfl_xor_sync(0xffffffffu, rs1, 1);
        rs1 += __shfl_xor_sync(0xffffffffu, rs1, 2);
        l0 = l0 * fac0 + rs0;
        l1 = l1 * fac1 + rs1;

        #pragma unroll
        for (int n = 0; n < 8; n++) {
            O[n][0] *= fac0; O[n][1] *= fac0;
            O[n][2] *= fac1; O[n][3] *= fac1;
        }

        // O += P*V : 4 k16 steps (j) x 8 n-tiles (dv); P chains in registers
        #pragma unroll
        for (int kk = 0; kk < 4; kk++) {
            unsigned a[4] = { pa[2 * kk][0], pa[2 * kk][1],
                              pa[2 * kk + 1][0], pa[2 * kk + 1][1] };
            #pragma unroll
            for (int n = 0; n < 8; n++) {
                int base = (8 * n + g) * 72 + 16 * kk + 2 * t4;
                unsigned b0 = *(const unsigned*)&Vb[base];
                unsigned b1 = *(const unsigned*)&Vb[base + 8];
                mma_f16(O[n], a, b0, b1);
            }
        }
        __syncthreads();   // all reads of buffer bb done before refill
    }

    // Epilogue: normalize, write g_Ah (fp16, feeds out-GEMM)
    int b = bh >> 3, h = bh & 7;
    float inv0 = 1.0f / l0;
    float inv1 = 1.0f / l1;
    #pragma unroll
    for (int n = 0; n < 8; n++) {
        int dv = 8 * n + 2 * t4;
        *(__half2*)&g_Ah[((size_t)b * T_ + r0) * D_ + h * HD_ + dv] =
            __floats2half2_rn(O[n][0] * inv0, O[n][1] * inv0);
        *(__half2*)&g_Ah[((size_t)b * T_ + r0 + 8) * D_ + h * HD_ + dv] =
            __floats2half2_rn(O[n][2] * inv1, O[n][3] * inv1);
    }
}

// ---------------------------------------------------------------------------
extern "C" void kernel_launch(void* const* d_in, const int* in_sizes, int n_in,
                              void* d_out, int out_size)
{
    const float* x     = (const float*)d_in[0];   // [4,2048,512]
    const float* W_qkv = (const float*)d_in[1];   // [512,1536]
    const float* b_qkv = (const float*)d_in[2];   // [1536]
    const float* W_out = (const float*)d_in[3];   // [512,512]
    const float* b_out = (const float*)d_in[4];   // [512]
    float* out = (float*)d_out;                   // [4,2048,512]

    cudaFuncSetAttribute(gemm_f16<1536, 1, 0, 0>,
                         cudaFuncAttributeMaxDynamicSharedMemorySize, GEMM_SMEM);
    cudaFuncSetAttribute(gemm_f16<512, 0, 1, 1>,
                         cudaFuncAttributeMaxDynamicSharedMemorySize, GEMM_SMEM);
    cudaFuncSetAttribute(attn_f16, cudaFuncAttributeMaxDynamicSharedMemorySize, ATTN_SMEM);

    conv_x_f16<<<4096, 256>>>(x);
    transpose_w<0><<<dim3(48, 16), dim3(32, 8)>>>(W_qkv, 512, 1536);
    transpose_w<1><<<dim3(16, 16), dim3(32, 8)>>>(W_out, 512, 512);
    gemm_f16<1536, 1, 0, 0><<<dim3(12, 64), 256, GEMM_SMEM>>>(b_qkv, nullptr);
    attn_f16<<<dim3(16, 32), 256, ATTN_SMEM>>>();
    gemm_f16<512, 0, 1, 1><<<dim3(4, 64), 256, GEMM_SMEM>>>(b_out, out);
}